// round 1
// baseline (speedup 1.0000x reference)
#include <cuda_runtime.h>
#include <math.h>

#define NN   50000
#define EE   800000
#define IN_DIM 128
#define O1   64
#define O2   128

// Scratch (device globals — no allocation allowed)
__device__ float g_deg[NN];
__device__ float g_dinv[NN];
__device__ float g_norm[EE];
__device__ float g_h1[NN * O1];
__device__ float g_z1[NN * O1];
__device__ float g_h2[NN * O2];

// ---------------------------------------------------------------------------
// helpers
// ---------------------------------------------------------------------------
__device__ __forceinline__ float canon_zero(float v) {
    // map -0.0f -> +0.0f so the atomic-max bit trick is order-correct
    return (__float_as_int(v) == (int)0x80000000) ? 0.0f : v;
}

__device__ __forceinline__ void atomicMaxF(float* addr, float v) {
    if (__float_as_int(v) == (int)0x80000000) v = 0.0f;
    if (v >= 0.0f) {
        atomicMax((int*)addr, __float_as_int(v));
    } else {
        atomicMin((unsigned int*)addr, __float_as_uint(v));
    }
}

// ---------------------------------------------------------------------------
// degree / norm
// ---------------------------------------------------------------------------
__global__ void k_init_deg() {
    int i = blockIdx.x * blockDim.x + threadIdx.x;
    if (i < NN) g_deg[i] = 2.0f;   // improved=True self-loop fill
}

__global__ void k_accum_deg(const int* __restrict__ ei, const float* __restrict__ ew) {
    int e = blockIdx.x * blockDim.x + threadIdx.x;
    if (e < EE) {
        float w = fmaxf(ew[e], 0.0f);          // relu(edge_weight)
        atomicAdd(&g_deg[ei[EE + e]], w);      // dst = ei[1]
    }
}

__global__ void k_dinv() {
    int i = blockIdx.x * blockDim.x + threadIdx.x;
    if (i < NN) {
        float d = g_deg[i];
        g_dinv[i] = (d > 0.0f) ? rsqrtf(fmaxf(d, 1e-30f)) : 0.0f;
    }
}

__global__ void k_norm(const int* __restrict__ ei, const float* __restrict__ ew) {
    int e = blockIdx.x * blockDim.x + threadIdx.x;
    if (e < EE) {
        float w = fmaxf(ew[e], 0.0f);
        g_norm[e] = g_dinv[ei[e]] * w * g_dinv[ei[EE + e]];
    }
}

// ---------------------------------------------------------------------------
// GEMM 1: h1[N,64] = x[N,128] @ W1[128,64]
// ---------------------------------------------------------------------------
__global__ void k_gemm1(const float* __restrict__ x, const float* __restrict__ W) {
    __shared__ float Ws[IN_DIM * O1];    // 32 KB
    __shared__ float xs[4][IN_DIM];      // 2 KB
    int j   = threadIdx.x;               // 0..63 output column
    int ty  = threadIdx.y;               // 0..3
    int tid = ty * 64 + j;
    for (int i = tid; i < IN_DIM * O1; i += 256) Ws[i] = W[i];
    int rowBase = blockIdx.x * 64;
    for (int rr = 0; rr < 64; rr += 4) {
        __syncthreads();
        for (int i = tid; i < 4 * IN_DIM; i += 256) {
            int r = i >> 7, k = i & 127;
            int nn = rowBase + rr + r;
            xs[r][k] = (nn < NN) ? x[nn * IN_DIM + k] : 0.0f;
        }
        __syncthreads();
        int n = rowBase + rr + ty;
        if (n < NN) {
            float acc = 0.0f;
#pragma unroll
            for (int k = 0; k < IN_DIM; k++)
                acc = fmaf(xs[ty][k], Ws[k * O1 + j], acc);
            g_h1[n * O1 + j] = acc;
        }
    }
}

// ---------------------------------------------------------------------------
// layer-1 max accumulator init (self-loop message) + edge scatter-max
// ---------------------------------------------------------------------------
__global__ void k_init_z1() {
    int idx = blockIdx.x * blockDim.x + threadIdx.x;
    if (idx < NN * O1) {
        int i = idx >> 6;
        float dv = g_dinv[i];
        g_z1[idx] = canon_zero(2.0f * dv * dv * g_h1[idx]);
    }
}

__global__ void k_scatter1(const int* __restrict__ ei) {
    int gt   = blockIdx.x * blockDim.x + threadIdx.x;
    int e    = gt >> 5;
    int lane = gt & 31;
    if (e >= EE) return;
    int s = ei[e], d = ei[EE + e];
    float nrm = g_norm[e];
    float2 hv = *(const float2*)(g_h1 + s * O1 + lane * 2);
    atomicMaxF(&g_z1[d * O1 + lane * 2    ], nrm * hv.x);
    atomicMaxF(&g_z1[d * O1 + lane * 2 + 1], nrm * hv.y);
}

// ---------------------------------------------------------------------------
// GEMM 2: h2[N,128] = (finite(z1)+b1)[N,64] @ W2[64,128]
// ---------------------------------------------------------------------------
__global__ void k_gemm2(const float* __restrict__ W2, const float* __restrict__ b1) {
    __shared__ float Ws[O1 * O2];        // 32 KB
    __shared__ float zs[2][O1];
    int j   = threadIdx.x;               // 0..127
    int ty  = threadIdx.y;               // 0..1
    int tid = ty * 128 + j;
    for (int i = tid; i < O1 * O2; i += 256) Ws[i] = W2[i];
    int rowBase = blockIdx.x * 64;
    for (int rr = 0; rr < 64; rr += 2) {
        __syncthreads();
        if (tid < 2 * O1) {
            int r = tid >> 6, k = tid & 63;
            int nn = rowBase + rr + r;
            float v = 0.0f;
            if (nn < NN) {
                v = g_z1[nn * O1 + k];
                if (!isfinite(v)) v = 0.0f;
                v += b1[k];
            }
            zs[r][k] = v;
        }
        __syncthreads();
        int n = rowBase + rr + ty;
        if (n < NN) {
            float acc = 0.0f;
#pragma unroll
            for (int k = 0; k < O1; k++)
                acc = fmaf(zs[ty][k], Ws[k * O2 + j], acc);
            g_h2[n * O2 + j] = acc;
        }
    }
}

// ---------------------------------------------------------------------------
// layer-2 init / scatter / finalize (accumulate directly in d_out)
// ---------------------------------------------------------------------------
__global__ void k_init_out(float* __restrict__ out) {
    int idx = blockIdx.x * blockDim.x + threadIdx.x;
    if (idx < NN * O2) {
        int i = idx >> 7;
        float dv = g_dinv[i];
        out[idx] = canon_zero(2.0f * dv * dv * g_h2[idx]);
    }
}

__global__ void k_scatter2(const int* __restrict__ ei, float* __restrict__ out) {
    int gt   = blockIdx.x * blockDim.x + threadIdx.x;
    int e    = gt >> 5;
    int lane = gt & 31;
    if (e >= EE) return;
    int s = ei[e], d = ei[EE + e];
    float nrm = g_norm[e];
    float4 hv = *(const float4*)(g_h2 + s * O2 + lane * 4);
    float* p = out + d * O2 + lane * 4;
    atomicMaxF(p + 0, nrm * hv.x);
    atomicMaxF(p + 1, nrm * hv.y);
    atomicMaxF(p + 2, nrm * hv.z);
    atomicMaxF(p + 3, nrm * hv.w);
}

__global__ void k_finalize(float* __restrict__ out, const float* __restrict__ b2) {
    int idx = blockIdx.x * blockDim.x + threadIdx.x;
    if (idx < NN * O2) {
        float v = out[idx];
        if (!isfinite(v)) v = 0.0f;
        out[idx] = v + b2[idx & 127];
    }
}

// ---------------------------------------------------------------------------
// host-side tower driver
// ---------------------------------------------------------------------------
static void run_tower(const float* x, const int* ei, const float* ew,
                      const float* W1, const float* b1,
                      const float* W2, const float* b2,
                      float* out) {
    const int TB = 256;
    k_init_deg <<<(NN + TB - 1) / TB, TB>>>();
    k_accum_deg<<<(EE + TB - 1) / TB, TB>>>(ei, ew);
    k_dinv     <<<(NN + TB - 1) / TB, TB>>>();
    k_norm     <<<(EE + TB - 1) / TB, TB>>>(ei, ew);

    dim3 g1b(64, 4);
    k_gemm1<<<(NN + 63) / 64, g1b>>>(x, W1);

    k_init_z1 <<<(NN * O1 + TB - 1) / TB, TB>>>();
    k_scatter1<<<(EE * 32 + TB - 1) / TB, TB>>>(ei);

    dim3 g2b(128, 2);
    k_gemm2<<<(NN + 63) / 64, g2b>>>(W2, b1);

    k_init_out<<<(NN * O2 + TB - 1) / TB, TB>>>(out);
    k_scatter2<<<(EE * 32 + TB - 1) / TB, TB>>>(ei, out);
    k_finalize<<<(NN * O2 + TB - 1) / TB, TB>>>(out, b2);
}

extern "C" void kernel_launch(void* const* d_in, const int* in_sizes, int n_in,
                              void* d_out, int out_size) {
    const float* x1  = (const float*)d_in[0];
    const int*   ei1 = (const int*)  d_in[1];
    const float* ew1 = (const float*)d_in[2];
    const float* x2  = (const float*)d_in[3];
    const int*   ei2 = (const int*)  d_in[4];
    const float* ew2 = (const float*)d_in[5];
    const float* W1  = (const float*)d_in[6];
    const float* b1  = (const float*)d_in[7];
    const float* W2  = (const float*)d_in[8];
    const float* b2  = (const float*)d_in[9];
    float* out = (float*)d_out;

    run_tower(x1, ei1, ew1, W1, b1, W2, b2, out);
    run_tower(x2, ei2, ew2, W1, b1, W2, b2, out + NN * O2);
}

// round 2
// speedup vs baseline: 1.9081x; 1.9081x over previous
#include <cuda_runtime.h>
#include <math.h>

#define NN   50000
#define EE   800000
#define IN_DIM 128
#define O1   64
#define O2   128

// Scratch (device globals — no allocation allowed)
__device__ float g_deg[NN];
__device__ float g_dinv[NN];
__device__ int   g_cnt[NN];
__device__ int   g_off[NN + 1];
__device__ int   g_cur[NN];
__device__ int   g_srcs[EE];
__device__ float g_wn[EE];
__device__ float g_h1[NN * O1];
__device__ float g_z1[NN * O1];
__device__ float g_h2[NN * O2];

// ---------------------------------------------------------------------------
// CSR build
// ---------------------------------------------------------------------------
__global__ void k_init() {
    int i = blockIdx.x * blockDim.x + threadIdx.x;
    if (i < NN) {
        g_deg[i] = 2.0f;   // improved=True self-loop fill
        g_cnt[i] = 0;
    }
}

__global__ void k_prep(const int* __restrict__ ei, const float* __restrict__ ew) {
    int e = blockIdx.x * blockDim.x + threadIdx.x;
    if (e < EE) {
        int d = ei[EE + e];
        float w = fmaxf(ew[e], 0.0f);          // relu(edge_weight)
        atomicAdd(&g_deg[d], w);
        atomicAdd(&g_cnt[d], 1);
    }
}

__global__ void k_dinv() {
    int i = blockIdx.x * blockDim.x + threadIdx.x;
    if (i < NN) {
        float d = g_deg[i];
        g_dinv[i] = (d > 0.0f) ? rsqrtf(fmaxf(d, 1e-30f)) : 0.0f;
    }
}

// single-block exclusive scan of g_cnt -> g_off  (50k elements)
__global__ void k_scan() {
    __shared__ int partial[1024];
    int t = threadIdx.x;
    const int CH = (NN + 1023) / 1024;   // 49
    int base = t * CH;
    int s = 0;
    for (int i = 0; i < CH; i++) {
        int idx = base + i;
        if (idx < NN) s += g_cnt[idx];
    }
    partial[t] = s;
    __syncthreads();
    for (int d = 1; d < 1024; d <<= 1) {
        int v = partial[t];
        int add = (t >= d) ? partial[t - d] : 0;
        __syncthreads();
        partial[t] = v + add;
        __syncthreads();
    }
    int run = (t == 0) ? 0 : partial[t - 1];
    for (int i = 0; i < CH; i++) {
        int idx = base + i;
        if (idx < NN) {
            g_off[idx] = run;
            g_cur[idx] = run;
            run += g_cnt[idx];
        }
    }
    if (t == 1023) g_off[NN] = run;   // == EE
}

__global__ void k_fill(const int* __restrict__ ei, const float* __restrict__ ew) {
    int e = blockIdx.x * blockDim.x + threadIdx.x;
    if (e < EE) {
        int s = ei[e], d = ei[EE + e];
        float w = fmaxf(ew[e], 0.0f);
        float nrm = g_dinv[s] * w * g_dinv[d];
        int pos = atomicAdd(&g_cur[d], 1);
        g_srcs[pos] = s;
        g_wn[pos]   = nrm;
    }
}

// ---------------------------------------------------------------------------
// GEMM 1: h1[N,64] = x[N,128] @ W1[128,64]
// ---------------------------------------------------------------------------
__global__ void k_gemm1(const float* __restrict__ x, const float* __restrict__ W) {
    __shared__ float Ws[IN_DIM * O1];    // 32 KB
    __shared__ float xs[4][IN_DIM];      // 2 KB
    int j   = threadIdx.x;               // 0..63 output column
    int ty  = threadIdx.y;               // 0..3
    int tid = ty * 64 + j;
    for (int i = tid; i < IN_DIM * O1; i += 256) Ws[i] = W[i];
    int rowBase = blockIdx.x * 64;
    for (int rr = 0; rr < 64; rr += 4) {
        __syncthreads();
        for (int i = tid; i < 4 * IN_DIM; i += 256) {
            int r = i >> 7, k = i & 127;
            int nn = rowBase + rr + r;
            xs[r][k] = (nn < NN) ? x[nn * IN_DIM + k] : 0.0f;
        }
        __syncthreads();
        int n = rowBase + rr + ty;
        if (n < NN) {
            float acc = 0.0f;
#pragma unroll
            for (int k = 0; k < IN_DIM; k++)
                acc = fmaf(xs[ty][k], Ws[k * O1 + j], acc);
            g_h1[n * O1 + j] = acc;
        }
    }
}

// ---------------------------------------------------------------------------
// Aggregation 1: warp per node, gather-max over CSR edges, fuse guard + b1
// ---------------------------------------------------------------------------
__global__ void k_aggr1(const float* __restrict__ b1) {
    int warp = (blockIdx.x * blockDim.x + threadIdx.x) >> 5;
    int lane = threadIdx.x & 31;
    if (warp >= NN) return;
    int beg = g_off[warp], end = g_off[warp + 1];
    float dv = g_dinv[warp];
    float sl = 2.0f * dv * dv;
    float2 self = *(const float2*)(g_h1 + warp * O1 + lane * 2);
    float m0 = sl * self.x;
    float m1 = sl * self.y;
    for (int j = beg; j < end; j++) {
        int s = g_srcs[j];
        float w = g_wn[j];
        float2 hv = *(const float2*)(g_h1 + s * O1 + lane * 2);
        m0 = fmaxf(m0, w * hv.x);
        m1 = fmaxf(m1, w * hv.y);
    }
    if (!isfinite(m0)) m0 = 0.0f;
    if (!isfinite(m1)) m1 = 0.0f;
    float2 bv = *(const float2*)(b1 + lane * 2);
    float2 r = make_float2(m0 + bv.x, m1 + bv.y);
    *(float2*)(g_z1 + warp * O1 + lane * 2) = r;
}

// ---------------------------------------------------------------------------
// GEMM 2: h2[N,128] = z1[N,64] @ W2[64,128]
// ---------------------------------------------------------------------------
__global__ void k_gemm2(const float* __restrict__ W2) {
    __shared__ float Ws[O1 * O2];        // 32 KB
    __shared__ float zs[2][O1];
    int j   = threadIdx.x;               // 0..127
    int ty  = threadIdx.y;               // 0..1
    int tid = ty * 128 + j;
    for (int i = tid; i < O1 * O2; i += 256) Ws[i] = W2[i];
    int rowBase = blockIdx.x * 64;
    for (int rr = 0; rr < 64; rr += 2) {
        __syncthreads();
        if (tid < 2 * O1) {
            int r = tid >> 6, k = tid & 63;
            int nn = rowBase + rr + r;
            zs[r][k] = (nn < NN) ? g_z1[nn * O1 + k] : 0.0f;
        }
        __syncthreads();
        int n = rowBase + rr + ty;
        if (n < NN) {
            float acc = 0.0f;
#pragma unroll
            for (int k = 0; k < O1; k++)
                acc = fmaf(zs[ty][k], Ws[k * O2 + j], acc);
            g_h2[n * O2 + j] = acc;
        }
    }
}

// ---------------------------------------------------------------------------
// Aggregation 2: warp per node over 128 feats (float4/lane), fuse guard + b2
// ---------------------------------------------------------------------------
__global__ void k_aggr2(const float* __restrict__ b2, float* __restrict__ out) {
    int warp = (blockIdx.x * blockDim.x + threadIdx.x) >> 5;
    int lane = threadIdx.x & 31;
    if (warp >= NN) return;
    int beg = g_off[warp], end = g_off[warp + 1];
    float dv = g_dinv[warp];
    float sl = 2.0f * dv * dv;
    float4 self = *(const float4*)(g_h2 + warp * O2 + lane * 4);
    float m0 = sl * self.x, m1 = sl * self.y, m2 = sl * self.z, m3 = sl * self.w;
    for (int j = beg; j < end; j++) {
        int s = g_srcs[j];
        float w = g_wn[j];
        float4 hv = *(const float4*)(g_h2 + s * O2 + lane * 4);
        m0 = fmaxf(m0, w * hv.x);
        m1 = fmaxf(m1, w * hv.y);
        m2 = fmaxf(m2, w * hv.z);
        m3 = fmaxf(m3, w * hv.w);
    }
    if (!isfinite(m0)) m0 = 0.0f;
    if (!isfinite(m1)) m1 = 0.0f;
    if (!isfinite(m2)) m2 = 0.0f;
    if (!isfinite(m3)) m3 = 0.0f;
    float4 bv = *(const float4*)(b2 + lane * 4);
    float4 r = make_float4(m0 + bv.x, m1 + bv.y, m2 + bv.z, m3 + bv.w);
    *(float4*)(out + warp * O2 + lane * 4) = r;
}

// ---------------------------------------------------------------------------
// host-side tower driver
// ---------------------------------------------------------------------------
static void run_tower(const float* x, const int* ei, const float* ew,
                      const float* W1, const float* b1,
                      const float* W2, const float* b2,
                      float* out) {
    const int TB = 256;
    k_init <<<(NN + TB - 1) / TB, TB>>>();
    k_prep <<<(EE + TB - 1) / TB, TB>>>(ei, ew);
    k_dinv <<<(NN + TB - 1) / TB, TB>>>();
    k_scan <<<1, 1024>>>();
    k_fill <<<(EE + TB - 1) / TB, TB>>>(ei, ew);

    dim3 g1b(64, 4);
    k_gemm1<<<(NN + 63) / 64, g1b>>>(x, W1);
    k_aggr1<<<(NN * 32 + TB - 1) / TB, TB>>>(b1);

    dim3 g2b(128, 2);
    k_gemm2<<<(NN + 63) / 64, g2b>>>(W2);
    k_aggr2<<<(NN * 32 + TB - 1) / TB, TB>>>(b2, out);
}

extern "C" void kernel_launch(void* const* d_in, const int* in_sizes, int n_in,
                              void* d_out, int out_size) {
    const float* x1  = (const float*)d_in[0];
    const int*   ei1 = (const int*)  d_in[1];
    const float* ew1 = (const float*)d_in[2];
    const float* x2  = (const float*)d_in[3];
    const int*   ei2 = (const int*)  d_in[4];
    const float* ew2 = (const float*)d_in[5];
    const float* W1  = (const float*)d_in[6];
    const float* b1  = (const float*)d_in[7];
    const float* W2  = (const float*)d_in[8];
    const float* b2  = (const float*)d_in[9];
    float* out = (float*)d_out;

    run_tower(x1, ei1, ew1, W1, b1, W2, b2, out);
    run_tower(x2, ei2, ew2, W1, b1, W2, b2, out + NN * O2);
}

// round 3
// speedup vs baseline: 2.4425x; 1.2801x over previous
#include <cuda_runtime.h>
#include <math.h>

#define NN   50000
#define EE   800000
#define IN_DIM 128
#define O1   64
#define O2   128

#define SCAN_B 1024
#define NBLK   ((NN + SCAN_B - 1) / SCAN_B)   // 49

// Scratch (device globals — no allocation allowed)
__device__ float g_deg[NN];
__device__ float g_dinv[NN];
__device__ int   g_cnt[NN];
__device__ int   g_off[NN + 1];
__device__ int   g_cur[NN];
__device__ int   g_blksum[64];
__device__ int   g_blkoff[64];
__device__ int   g_srcs[EE];
__device__ float g_wn[EE];
__device__ float g_h1[NN * O1];
__device__ float g_z1[NN * O1];
__device__ float g_h2[NN * O2];

// ---------------------------------------------------------------------------
// CSR build
// ---------------------------------------------------------------------------
__global__ void k_init() {
    int i = blockIdx.x * blockDim.x + threadIdx.x;
    if (i < NN) {
        g_deg[i] = 2.0f;   // improved=True self-loop fill
        g_cnt[i] = 0;
    }
}

__global__ void k_prep(const int* __restrict__ ei, const float* __restrict__ ew) {
    int e = blockIdx.x * blockDim.x + threadIdx.x;
    if (e < EE) {
        int d = ei[EE + e];
        float w = fmaxf(ew[e], 0.0f);          // relu(edge_weight)
        atomicAdd(&g_deg[d], w);
        atomicAdd(&g_cnt[d], 1);
    }
}

// phase 1: per-block exclusive partials + block sums
__global__ void k_scan1() {
    int i    = blockIdx.x * SCAN_B + threadIdx.x;
    int lane = threadIdx.x & 31;
    int wid  = threadIdx.x >> 5;
    int c = (i < NN) ? g_cnt[i] : 0;
    int v = c;
#pragma unroll
    for (int d = 1; d < 32; d <<= 1) {
        int t = __shfl_up_sync(0xffffffffu, v, d);
        if (lane >= d) v += t;
    }
    __shared__ int wsum[32];
    if (lane == 31) wsum[wid] = v;
    __syncthreads();
    if (wid == 0) {
        int w = wsum[lane];
#pragma unroll
        for (int d = 1; d < 32; d <<= 1) {
            int t = __shfl_up_sync(0xffffffffu, w, d);
            if (lane >= d) w += t;
        }
        wsum[lane] = w;
    }
    __syncthreads();
    int add = (wid > 0) ? wsum[wid - 1] : 0;
    if (i < NN) g_off[i] = v + add - c;                 // exclusive within block
    if (threadIdx.x == SCAN_B - 1) g_blksum[blockIdx.x] = wsum[31];
}

// phase 2: scan the 49 block sums (tiny)
__global__ void k_scan2() {
    __shared__ int s[64];
    int t = threadIdx.x;           // 64 threads
    s[t] = (t < NBLK) ? g_blksum[t] : 0;
    __syncthreads();
#pragma unroll
    for (int d = 1; d < 64; d <<= 1) {
        int v = s[t];
        int a = (t >= d) ? s[t - d] : 0;
        __syncthreads();
        s[t] = v + a;
        __syncthreads();
    }
    if (t < NBLK) g_blkoff[t] = (t == 0) ? 0 : s[t - 1];
}

// phase 3: add block offsets, init g_cur, fuse dinv
__global__ void k_scan3() {
    int i = blockIdx.x * blockDim.x + threadIdx.x;
    if (i < NN) {
        int o = g_off[i] + g_blkoff[i / SCAN_B];
        g_off[i] = o;
        g_cur[i] = o;
        float d = g_deg[i];
        g_dinv[i] = (d > 0.0f) ? rsqrtf(fmaxf(d, 1e-30f)) : 0.0f;
    }
    if (i == 0) g_off[NN] = EE;    // total count is always EE
}

__global__ void k_fill(const int* __restrict__ ei, const float* __restrict__ ew) {
    int e = blockIdx.x * blockDim.x + threadIdx.x;
    if (e < EE) {
        int s = ei[e], d = ei[EE + e];
        float w = fmaxf(ew[e], 0.0f);
        float nrm = g_dinv[s] * w * g_dinv[d];
        int pos = atomicAdd(&g_cur[d], 1);
        g_srcs[pos] = s;
        g_wn[pos]   = nrm;
    }
}

// ---------------------------------------------------------------------------
// GEMM 1: h1[N,64] = x[N,128] @ W1[128,64]
// ---------------------------------------------------------------------------
__global__ void k_gemm1(const float* __restrict__ x, const float* __restrict__ W) {
    __shared__ float Ws[IN_DIM * O1];    // 32 KB
    __shared__ float xs[4][IN_DIM];      // 2 KB
    int j   = threadIdx.x;               // 0..63 output column
    int ty  = threadIdx.y;               // 0..3
    int tid = ty * 64 + j;
    for (int i = tid; i < IN_DIM * O1; i += 256) Ws[i] = W[i];
    int rowBase = blockIdx.x * 64;
    for (int rr = 0; rr < 64; rr += 4) {
        __syncthreads();
        for (int i = tid; i < 4 * IN_DIM; i += 256) {
            int r = i >> 7, k = i & 127;
            int nn = rowBase + rr + r;
            xs[r][k] = (nn < NN) ? x[nn * IN_DIM + k] : 0.0f;
        }
        __syncthreads();
        int n = rowBase + rr + ty;
        if (n < NN) {
            float acc = 0.0f;
#pragma unroll
            for (int k = 0; k < IN_DIM; k++)
                acc = fmaf(xs[ty][k], Ws[k * O1 + j], acc);
            g_h1[n * O1 + j] = acc;
        }
    }
}

// ---------------------------------------------------------------------------
// Aggregation 1: warp per node, gather-max over CSR edges, fuse guard + b1
// ---------------------------------------------------------------------------
__global__ void k_aggr1(const float* __restrict__ b1) {
    int warp = (blockIdx.x * blockDim.x + threadIdx.x) >> 5;
    int lane = threadIdx.x & 31;
    if (warp >= NN) return;
    int beg = g_off[warp], end = g_off[warp + 1];
    float dv = g_dinv[warp];
    float sl = 2.0f * dv * dv;
    float2 self = *(const float2*)(g_h1 + warp * O1 + lane * 2);
    float m0 = sl * self.x;
    float m1 = sl * self.y;
    for (int j = beg; j < end; j++) {
        int s = g_srcs[j];
        float w = g_wn[j];
        float2 hv = *(const float2*)(g_h1 + s * O1 + lane * 2);
        m0 = fmaxf(m0, w * hv.x);
        m1 = fmaxf(m1, w * hv.y);
    }
    if (!isfinite(m0)) m0 = 0.0f;
    if (!isfinite(m1)) m1 = 0.0f;
    float2 bv = *(const float2*)(b1 + lane * 2);
    float2 r = make_float2(m0 + bv.x, m1 + bv.y);
    *(float2*)(g_z1 + warp * O1 + lane * 2) = r;
}

// ---------------------------------------------------------------------------
// GEMM 2: h2[N,128] = z1[N,64] @ W2[64,128]
// ---------------------------------------------------------------------------
__global__ void k_gemm2(const float* __restrict__ W2) {
    __shared__ float Ws[O1 * O2];        // 32 KB
    __shared__ float zs[2][O1];
    int j   = threadIdx.x;               // 0..127
    int ty  = threadIdx.y;               // 0..1
    int tid = ty * 128 + j;
    for (int i = tid; i < O1 * O2; i += 256) Ws[i] = W2[i];
    int rowBase = blockIdx.x * 64;
    for (int rr = 0; rr < 64; rr += 2) {
        __syncthreads();
        if (tid < 2 * O1) {
            int r = tid >> 6, k = tid & 63;
            int nn = rowBase + rr + r;
            zs[r][k] = (nn < NN) ? g_z1[nn * O1 + k] : 0.0f;
        }
        __syncthreads();
        int n = rowBase + rr + ty;
        if (n < NN) {
            float acc = 0.0f;
#pragma unroll
            for (int k = 0; k < O1; k++)
                acc = fmaf(zs[ty][k], Ws[k * O2 + j], acc);
            g_h2[n * O2 + j] = acc;
        }
    }
}

// ---------------------------------------------------------------------------
// Aggregation 2: warp per node over 128 feats (float4/lane), fuse guard + b2
// ---------------------------------------------------------------------------
__global__ void k_aggr2(const float* __restrict__ b2, float* __restrict__ out) {
    int warp = (blockIdx.x * blockDim.x + threadIdx.x) >> 5;
    int lane = threadIdx.x & 31;
    if (warp >= NN) return;
    int beg = g_off[warp], end = g_off[warp + 1];
    float dv = g_dinv[warp];
    float sl = 2.0f * dv * dv;
    float4 self = *(const float4*)(g_h2 + warp * O2 + lane * 4);
    float m0 = sl * self.x, m1 = sl * self.y, m2 = sl * self.z, m3 = sl * self.w;
    for (int j = beg; j < end; j++) {
        int s = g_srcs[j];
        float w = g_wn[j];
        float4 hv = *(const float4*)(g_h2 + s * O2 + lane * 4);
        m0 = fmaxf(m0, w * hv.x);
        m1 = fmaxf(m1, w * hv.y);
        m2 = fmaxf(m2, w * hv.z);
        m3 = fmaxf(m3, w * hv.w);
    }
    if (!isfinite(m0)) m0 = 0.0f;
    if (!isfinite(m1)) m1 = 0.0f;
    if (!isfinite(m2)) m2 = 0.0f;
    if (!isfinite(m3)) m3 = 0.0f;
    float4 bv = *(const float4*)(b2 + lane * 4);
    float4 r = make_float4(m0 + bv.x, m1 + bv.y, m2 + bv.z, m3 + bv.w);
    *(float4*)(out + warp * O2 + lane * 4) = r;
}

// ---------------------------------------------------------------------------
// host-side tower driver
// ---------------------------------------------------------------------------
static void run_tower(const float* x, const int* ei, const float* ew,
                      const float* W1, const float* b1,
                      const float* W2, const float* b2,
                      float* out) {
    const int TB = 256;
    k_init <<<(NN + TB - 1) / TB, TB>>>();
    k_prep <<<(EE + TB - 1) / TB, TB>>>(ei, ew);
    k_scan1<<<NBLK, SCAN_B>>>();
    k_scan2<<<1, 64>>>();
    k_scan3<<<(NN + TB - 1) / TB, TB>>>();
    k_fill <<<(EE + TB - 1) / TB, TB>>>(ei, ew);

    dim3 g1b(64, 4);
    k_gemm1<<<(NN + 63) / 64, g1b>>>(x, W1);
    k_aggr1<<<(NN * 32 + TB - 1) / TB, TB>>>(b1);

    dim3 g2b(128, 2);
    k_gemm2<<<(NN + 63) / 64, g2b>>>(W2);
    k_aggr2<<<(NN * 32 + TB - 1) / TB, TB>>>(b2, out);
}

extern "C" void kernel_launch(void* const* d_in, const int* in_sizes, int n_in,
                              void* d_out, int out_size) {
    const float* x1  = (const float*)d_in[0];
    const int*   ei1 = (const int*)  d_in[1];
    const float* ew1 = (const float*)d_in[2];
    const float* x2  = (const float*)d_in[3];
    const int*   ei2 = (const int*)  d_in[4];
    const float* ew2 = (const float*)d_in[5];
    const float* W1  = (const float*)d_in[6];
    const float* b1  = (const float*)d_in[7];
    const float* W2  = (const float*)d_in[8];
    const float* b2  = (const float*)d_in[9];
    float* out = (float*)d_out;

    run_tower(x1, ei1, ew1, W1, b1, W2, b2, out);
    run_tower(x2, ei2, ew2, W1, b1, W2, b2, out + NN * O2);
}

// round 4
// speedup vs baseline: 3.7910x; 1.5521x over previous
#include <cuda_runtime.h>
#include <math.h>

#define NN   50000
#define EE   800000
#define IN_DIM 128
#define O1   64
#define O2   128

#define SCAN_B 1024
#define NBLK   ((NN + SCAN_B - 1) / SCAN_B)   // 49

// Scratch (device globals — no allocation allowed). Index 0/1 = tower.
__device__ float g_deg [2][NN];
__device__ float g_dinv[2][NN];
__device__ int   g_cnt [2][NN];
__device__ int   g_off [2][NN + 1];
__device__ int   g_cur [2][NN];
__device__ int   g_blksum[2][64];
__device__ int   g_blkoff[2][64];
__device__ int2  g_edge[2][EE];          // (src, float-bits of norm)
__device__ float g_h1[2][NN * O1];
__device__ float g_z1[2][NN * O1];
__device__ float g_h2[2][NN * O2];

// ---------------------------------------------------------------------------
// packed fp32x2 FMA (sm_103a FFMA2)
// ---------------------------------------------------------------------------
__device__ __forceinline__ void ffma2(float2& acc, float2 a, float2 w) {
    unsigned long long ac, av, wv;
    ac = *(unsigned long long*)&acc;
    av = *(unsigned long long*)&a;
    wv = *(unsigned long long*)&w;
    asm("fma.rn.f32x2 %0, %1, %2, %0;" : "+l"(ac) : "l"(av), "l"(wv));
    acc = *(float2*)&ac;
}

// ---------------------------------------------------------------------------
// CSR build
// ---------------------------------------------------------------------------
__global__ void k_init() {
    int tw = blockIdx.y;
    int i = blockIdx.x * blockDim.x + threadIdx.x;
    if (i < NN) {
        g_deg[tw][i] = 2.0f;   // improved=True self-loop fill
        g_cnt[tw][i] = 0;
    }
}

__global__ void k_prep(const int* __restrict__ ei1, const float* __restrict__ ew1,
                       const int* __restrict__ ei2, const float* __restrict__ ew2) {
    int tw = blockIdx.y;
    const int*   ei = tw ? ei2 : ei1;
    const float* ew = tw ? ew2 : ew1;
    int e = blockIdx.x * blockDim.x + threadIdx.x;
    if (e < EE) {
        int d = ei[EE + e];
        float w = fmaxf(ew[e], 0.0f);          // relu(edge_weight)
        atomicAdd(&g_deg[tw][d], w);
        atomicAdd(&g_cnt[tw][d], 1);
    }
}

// phase 1: per-block exclusive partials + block sums
__global__ void k_scan1() {
    int tw   = blockIdx.y;
    int i    = blockIdx.x * SCAN_B + threadIdx.x;
    int lane = threadIdx.x & 31;
    int wid  = threadIdx.x >> 5;
    int c = (i < NN) ? g_cnt[tw][i] : 0;
    int v = c;
#pragma unroll
    for (int d = 1; d < 32; d <<= 1) {
        int t = __shfl_up_sync(0xffffffffu, v, d);
        if (lane >= d) v += t;
    }
    __shared__ int wsum[32];
    if (lane == 31) wsum[wid] = v;
    __syncthreads();
    if (wid == 0) {
        int w = wsum[lane];
#pragma unroll
        for (int d = 1; d < 32; d <<= 1) {
            int t = __shfl_up_sync(0xffffffffu, w, d);
            if (lane >= d) w += t;
        }
        wsum[lane] = w;
    }
    __syncthreads();
    int add = (wid > 0) ? wsum[wid - 1] : 0;
    if (i < NN) g_off[tw][i] = v + add - c;                 // exclusive within block
    if (threadIdx.x == SCAN_B - 1) g_blksum[tw][blockIdx.x] = wsum[31];
}

// phase 2: scan the 49 block sums (tiny)
__global__ void k_scan2() {
    int tw = blockIdx.y;
    __shared__ int s[64];
    int t = threadIdx.x;           // 64 threads
    s[t] = (t < NBLK) ? g_blksum[tw][t] : 0;
    __syncthreads();
#pragma unroll
    for (int d = 1; d < 64; d <<= 1) {
        int v = s[t];
        int a = (t >= d) ? s[t - d] : 0;
        __syncthreads();
        s[t] = v + a;
        __syncthreads();
    }
    if (t < NBLK) g_blkoff[tw][t] = (t == 0) ? 0 : s[t - 1];
}

// phase 3: add block offsets, init g_cur, fuse dinv
__global__ void k_scan3() {
    int tw = blockIdx.y;
    int i = blockIdx.x * blockDim.x + threadIdx.x;
    if (i < NN) {
        int o = g_off[tw][i] + g_blkoff[tw][i / SCAN_B];
        g_off[tw][i] = o;
        g_cur[tw][i] = o;
        float d = g_deg[tw][i];
        g_dinv[tw][i] = (d > 0.0f) ? rsqrtf(fmaxf(d, 1e-30f)) : 0.0f;
    }
    if (i == 0) g_off[tw][NN] = EE;    // total count is always EE
}

__global__ void k_fill(const int* __restrict__ ei1, const float* __restrict__ ew1,
                       const int* __restrict__ ei2, const float* __restrict__ ew2) {
    int tw = blockIdx.y;
    const int*   ei = tw ? ei2 : ei1;
    const float* ew = tw ? ew2 : ew1;
    int e = blockIdx.x * blockDim.x + threadIdx.x;
    if (e < EE) {
        int s = ei[e], d = ei[EE + e];
        float w = fmaxf(ew[e], 0.0f);
        float nrm = g_dinv[tw][s] * w * g_dinv[tw][d];
        int pos = atomicAdd(&g_cur[tw][d], 1);
        g_edge[tw][pos] = make_int2(s, __float_as_int(nrm));
    }
}

// ---------------------------------------------------------------------------
// Register-tiled GEMM: C[N,OC-tile] = A[N,K] @ W[K,OC], block = 64 rows x 64 cols
// threads (16,16); each thread 4 rows x 4 cols; k paired for fma.rn.f32x2
// ---------------------------------------------------------------------------
template<int K, int OC>
__device__ __forceinline__ void gemm_body(const float* __restrict__ A,
                                          const float* __restrict__ W,
                                          float* __restrict__ C) {
    __shared__ float2 Wp[(K / 2) * 64];   // Wp[kp*64 + c] = (W[2kp][c], W[2kp+1][c])
    int tx  = threadIdx.x;                // 0..15 -> cols
    int ty  = threadIdx.y;                // 0..15 -> rows
    int tid = ty * 16 + tx;
    int colBase = blockIdx.y * 64;
    for (int idx = tid; idx < (K / 2) * 64; idx += 256) {
        int kp = idx >> 6, c = idx & 63;
        Wp[idx] = make_float2(W[(2 * kp)     * OC + colBase + c],
                              W[(2 * kp + 1) * OC + colBase + c]);
    }
    __syncthreads();

    int r0 = blockIdx.x * 64 + ty * 4;
    int c0 = tx * 4;
    float2 acc[4][4];
#pragma unroll
    for (int i = 0; i < 4; i++)
#pragma unroll
        for (int j = 0; j < 4; j++) acc[i][j] = make_float2(0.0f, 0.0f);

#pragma unroll 4
    for (int kk = 0; kk < K; kk += 4) {
        float4 a[4];
#pragma unroll
        for (int i = 0; i < 4; i++) {
            int r = r0 + i;
            a[i] = (r < NN) ? *(const float4*)(A + (size_t)r * K + kk)
                            : make_float4(0.0f, 0.0f, 0.0f, 0.0f);
        }
#pragma unroll
        for (int kp = 0; kp < 2; kp++) {
            const float2* wrow = Wp + ((kk >> 1) + kp) * 64 + c0;
            float4 wA = *(const float4*)(wrow);       // cols c0, c0+1
            float4 wB = *(const float4*)(wrow + 2);   // cols c0+2, c0+3
            float2 w0 = make_float2(wA.x, wA.y);
            float2 w1 = make_float2(wA.z, wA.w);
            float2 w2 = make_float2(wB.x, wB.y);
            float2 w3 = make_float2(wB.z, wB.w);
#pragma unroll
            for (int i = 0; i < 4; i++) {
                float2 ap = kp ? make_float2(a[i].z, a[i].w)
                               : make_float2(a[i].x, a[i].y);
                ffma2(acc[i][0], ap, w0);
                ffma2(acc[i][1], ap, w1);
                ffma2(acc[i][2], ap, w2);
                ffma2(acc[i][3], ap, w3);
            }
        }
    }
#pragma unroll
    for (int i = 0; i < 4; i++) {
        int r = r0 + i;
        if (r < NN) {
            float4 o;
            o.x = acc[i][0].x + acc[i][0].y;
            o.y = acc[i][1].x + acc[i][1].y;
            o.z = acc[i][2].x + acc[i][2].y;
            o.w = acc[i][3].x + acc[i][3].y;
            *(float4*)(C + (size_t)r * OC + colBase + c0) = o;
        }
    }
}

__global__ void k_gemm1(const float* __restrict__ x1, const float* __restrict__ x2,
                        const float* __restrict__ W1) {
    int tw = blockIdx.z;
    gemm_body<IN_DIM, O1>(tw ? x2 : x1, W1, g_h1[tw]);
}

__global__ void k_gemm2(const float* __restrict__ W2) {
    int tw = blockIdx.z;
    gemm_body<O1, O2>(g_z1[tw], W2, g_h2[tw]);
}

// ---------------------------------------------------------------------------
// Aggregation 1: warp per node, gather-max over CSR edges (4x unrolled, MLP=4)
// ---------------------------------------------------------------------------
__global__ void k_aggr1(const float* __restrict__ b1) {
    int tw   = blockIdx.y;
    int warp = (blockIdx.x * blockDim.x + threadIdx.x) >> 5;
    int lane = threadIdx.x & 31;
    if (warp >= NN) return;
    const int2*  eg = g_edge[tw];
    const float* h  = g_h1[tw];
    int beg = g_off[tw][warp], end = g_off[tw][warp + 1];
    float dv = g_dinv[tw][warp];
    float sl = 2.0f * dv * dv;
    float2 self = *(const float2*)(h + (size_t)warp * O1 + lane * 2);
    float m0 = sl * self.x;
    float m1 = sl * self.y;
    int j = beg;
    for (; j + 4 <= end; j += 4) {
        int2 e0 = eg[j], e1 = eg[j + 1], e2 = eg[j + 2], e3 = eg[j + 3];
        float2 v0 = *(const float2*)(h + (size_t)e0.x * O1 + lane * 2);
        float2 v1 = *(const float2*)(h + (size_t)e1.x * O1 + lane * 2);
        float2 v2 = *(const float2*)(h + (size_t)e2.x * O1 + lane * 2);
        float2 v3 = *(const float2*)(h + (size_t)e3.x * O1 + lane * 2);
        float w0 = __int_as_float(e0.y), w1 = __int_as_float(e1.y);
        float w2 = __int_as_float(e2.y), w3 = __int_as_float(e3.y);
        m0 = fmaxf(m0, w0 * v0.x); m1 = fmaxf(m1, w0 * v0.y);
        m0 = fmaxf(m0, w1 * v1.x); m1 = fmaxf(m1, w1 * v1.y);
        m0 = fmaxf(m0, w2 * v2.x); m1 = fmaxf(m1, w2 * v2.y);
        m0 = fmaxf(m0, w3 * v3.x); m1 = fmaxf(m1, w3 * v3.y);
    }
    for (; j < end; j++) {
        int2 e = eg[j];
        float w = __int_as_float(e.y);
        float2 v = *(const float2*)(h + (size_t)e.x * O1 + lane * 2);
        m0 = fmaxf(m0, w * v.x);
        m1 = fmaxf(m1, w * v.y);
    }
    if (!isfinite(m0)) m0 = 0.0f;
    if (!isfinite(m1)) m1 = 0.0f;
    float2 bv = *(const float2*)(b1 + lane * 2);
    *(float2*)(g_z1[tw] + (size_t)warp * O1 + lane * 2) = make_float2(m0 + bv.x, m1 + bv.y);
}

// ---------------------------------------------------------------------------
// Aggregation 2: warp per node over 128 feats (float4/lane), 4x unrolled
// ---------------------------------------------------------------------------
__global__ void k_aggr2(const float* __restrict__ b2, float* __restrict__ out) {
    int tw   = blockIdx.y;
    int warp = (blockIdx.x * blockDim.x + threadIdx.x) >> 5;
    int lane = threadIdx.x & 31;
    if (warp >= NN) return;
    const int2*  eg = g_edge[tw];
    const float* h  = g_h2[tw];
    float* op = out + (size_t)tw * NN * O2;
    int beg = g_off[tw][warp], end = g_off[tw][warp + 1];
    float dv = g_dinv[tw][warp];
    float sl = 2.0f * dv * dv;
    float4 self = *(const float4*)(h + (size_t)warp * O2 + lane * 4);
    float m0 = sl * self.x, m1 = sl * self.y, m2 = sl * self.z, m3 = sl * self.w;
    int j = beg;
    for (; j + 4 <= end; j += 4) {
        int2 e0 = eg[j], e1 = eg[j + 1], e2 = eg[j + 2], e3 = eg[j + 3];
        float4 v0 = *(const float4*)(h + (size_t)e0.x * O2 + lane * 4);
        float4 v1 = *(const float4*)(h + (size_t)e1.x * O2 + lane * 4);
        float4 v2 = *(const float4*)(h + (size_t)e2.x * O2 + lane * 4);
        float4 v3 = *(const float4*)(h + (size_t)e3.x * O2 + lane * 4);
        float w0 = __int_as_float(e0.y), w1 = __int_as_float(e1.y);
        float w2 = __int_as_float(e2.y), w3 = __int_as_float(e3.y);
        m0 = fmaxf(m0, w0 * v0.x); m1 = fmaxf(m1, w0 * v0.y);
        m2 = fmaxf(m2, w0 * v0.z); m3 = fmaxf(m3, w0 * v0.w);
        m0 = fmaxf(m0, w1 * v1.x); m1 = fmaxf(m1, w1 * v1.y);
        m2 = fmaxf(m2, w1 * v1.z); m3 = fmaxf(m3, w1 * v1.w);
        m0 = fmaxf(m0, w2 * v2.x); m1 = fmaxf(m1, w2 * v2.y);
        m2 = fmaxf(m2, w2 * v2.z); m3 = fmaxf(m3, w2 * v2.w);
        m0 = fmaxf(m0, w3 * v3.x); m1 = fmaxf(m1, w3 * v3.y);
        m2 = fmaxf(m2, w3 * v3.z); m3 = fmaxf(m3, w3 * v3.w);
    }
    for (; j < end; j++) {
        int2 e = eg[j];
        float w = __int_as_float(e.y);
        float4 v = *(const float4*)(h + (size_t)e.x * O2 + lane * 4);
        m0 = fmaxf(m0, w * v.x); m1 = fmaxf(m1, w * v.y);
        m2 = fmaxf(m2, w * v.z); m3 = fmaxf(m3, w * v.w);
    }
    if (!isfinite(m0)) m0 = 0.0f;
    if (!isfinite(m1)) m1 = 0.0f;
    if (!isfinite(m2)) m2 = 0.0f;
    if (!isfinite(m3)) m3 = 0.0f;
    float4 bv = *(const float4*)(b2 + lane * 4);
    *(float4*)(op + (size_t)warp * O2 + lane * 4) =
        make_float4(m0 + bv.x, m1 + bv.y, m2 + bv.z, m3 + bv.w);
}

// ---------------------------------------------------------------------------
// launch
// ---------------------------------------------------------------------------
extern "C" void kernel_launch(void* const* d_in, const int* in_sizes, int n_in,
                              void* d_out, int out_size) {
    const float* x1  = (const float*)d_in[0];
    const int*   ei1 = (const int*)  d_in[1];
    const float* ew1 = (const float*)d_in[2];
    const float* x2  = (const float*)d_in[3];
    const int*   ei2 = (const int*)  d_in[4];
    const float* ew2 = (const float*)d_in[5];
    const float* W1  = (const float*)d_in[6];
    const float* b1  = (const float*)d_in[7];
    const float* W2  = (const float*)d_in[8];
    const float* b2  = (const float*)d_in[9];
    float* out = (float*)d_out;

    const int TB = 256;
    k_init <<<dim3((NN + TB - 1) / TB, 2), TB>>>();
    k_prep <<<dim3((EE + TB - 1) / TB, 2), TB>>>(ei1, ew1, ei2, ew2);
    k_scan1<<<dim3(NBLK, 2), SCAN_B>>>();
    k_scan2<<<dim3(1, 2), 64>>>();
    k_scan3<<<dim3((NN + TB - 1) / TB, 2), TB>>>();
    k_fill <<<dim3((EE + TB - 1) / TB, 2), TB>>>(ei1, ew1, ei2, ew2);

    dim3 gblk(16, 16);
    k_gemm1<<<dim3((NN + 63) / 64, 1, 2), gblk>>>(x1, x2, W1);
    k_aggr1<<<dim3((NN * 32 + TB - 1) / TB, 2), TB>>>(b1);
    k_gemm2<<<dim3((NN + 63) / 64, 2, 2), gblk>>>(W2);
    k_aggr2<<<dim3((NN * 32 + TB - 1) / TB, 2), TB>>>(b2, out);
}

// round 5
// speedup vs baseline: 3.9522x; 1.0425x over previous
#include <cuda_runtime.h>
#include <math.h>

#define NN   50000
#define EE   800000
#define IN_DIM 128
#define O1   64
#define O2   128

#define SCAN_B 1024
#define NBLK   ((NN + SCAN_B - 1) / SCAN_B)   // 49

#define PREP_BLOCKS ((EE + 255) / 256)        // 3125
#define G1_BLOCKS   ((NN + 63) / 64)          // 782

// Scratch (device globals — no allocation allowed). Index 0/1 = tower.
__device__ float g_deg [2][NN];
__device__ float g_dinv[2][NN];
__device__ int   g_cnt [2][NN];
__device__ int   g_off [2][NN + 1];
__device__ int   g_cur [2][NN];
__device__ int   g_blksum[2][64];
__device__ int2  g_edge[2][EE];          // (src, float-bits of norm)
__device__ float g_h1[2][NN * O1];
__device__ float g_z1[2][NN * O1];
__device__ float g_h2[2][NN * O2];

// ---------------------------------------------------------------------------
// packed fp32x2 FMA (sm_103a FFMA2)
// ---------------------------------------------------------------------------
__device__ __forceinline__ void ffma2(float2& acc, float2 a, float2 w) {
    unsigned long long ac, av, wv;
    ac = *(unsigned long long*)&acc;
    av = *(unsigned long long*)&a;
    wv = *(unsigned long long*)&w;
    asm("fma.rn.f32x2 %0, %1, %2, %0;" : "+l"(ac) : "l"(av), "l"(wv));
    acc = *(float2*)&ac;
}

// ---------------------------------------------------------------------------
// Register-tiled GEMM body: C[64-row tile, 64-col tile] = A[N,K] @ W[K,OC]
// 256 flat threads; each thread 4 rows x 4 cols; k paired for fma.rn.f32x2
// ---------------------------------------------------------------------------
template<int K, int OC>
__device__ __forceinline__ void gemm_body(const float* __restrict__ A,
                                          const float* __restrict__ W,
                                          float* __restrict__ C,
                                          int rowBlk, int colBase, int tid) {
    __shared__ float2 Wp[(K / 2) * 64];   // Wp[kp*64 + c] = (W[2kp][c], W[2kp+1][c])
    int tx = tid & 15;                    // cols
    int ty = tid >> 4;                    // rows
    for (int idx = tid; idx < (K / 2) * 64; idx += 256) {
        int kp = idx >> 6, c = idx & 63;
        Wp[idx] = make_float2(W[(2 * kp)     * OC + colBase + c],
                              W[(2 * kp + 1) * OC + colBase + c]);
    }
    __syncthreads();

    int r0 = rowBlk * 64 + ty * 4;
    int c0 = tx * 4;
    float2 acc[4][4];
#pragma unroll
    for (int i = 0; i < 4; i++)
#pragma unroll
        for (int j = 0; j < 4; j++) acc[i][j] = make_float2(0.0f, 0.0f);

#pragma unroll 4
    for (int kk = 0; kk < K; kk += 4) {
        float4 a[4];
#pragma unroll
        for (int i = 0; i < 4; i++) {
            int r = r0 + i;
            a[i] = (r < NN) ? *(const float4*)(A + (size_t)r * K + kk)
                            : make_float4(0.0f, 0.0f, 0.0f, 0.0f);
        }
#pragma unroll
        for (int kp = 0; kp < 2; kp++) {
            const float2* wrow = Wp + ((kk >> 1) + kp) * 64 + c0;
            float4 wA = *(const float4*)(wrow);       // cols c0, c0+1
            float4 wB = *(const float4*)(wrow + 2);   // cols c0+2, c0+3
            float2 w0 = make_float2(wA.x, wA.y);
            float2 w1 = make_float2(wA.z, wA.w);
            float2 w2 = make_float2(wB.x, wB.y);
            float2 w3 = make_float2(wB.z, wB.w);
#pragma unroll
            for (int i = 0; i < 4; i++) {
                float2 ap = kp ? make_float2(a[i].z, a[i].w)
                               : make_float2(a[i].x, a[i].y);
                ffma2(acc[i][0], ap, w0);
                ffma2(acc[i][1], ap, w1);
                ffma2(acc[i][2], ap, w2);
                ffma2(acc[i][3], ap, w3);
            }
        }
    }
#pragma unroll
    for (int i = 0; i < 4; i++) {
        int r = r0 + i;
        if (r < NN) {
            float4 o;
            o.x = acc[i][0].x + acc[i][0].y;
            o.y = acc[i][1].x + acc[i][1].y;
            o.z = acc[i][2].x + acc[i][2].y;
            o.w = acc[i][3].x + acc[i][3].y;
            *(float4*)(C + (size_t)r * OC + colBase + c0) = o;
        }
    }
}

// ---------------------------------------------------------------------------
// init
// ---------------------------------------------------------------------------
__global__ void k_init() {
    int tw = blockIdx.y;
    int i = blockIdx.x * blockDim.x + threadIdx.x;
    if (i < NN) {
        g_deg[tw][i] = 2.0f;   // improved=True self-loop fill
        g_cnt[tw][i] = 0;
    }
}

// ---------------------------------------------------------------------------
// fused: deg/count atomics (blocks [0,PREP_BLOCKS)) | GEMM1 (the rest)
// ---------------------------------------------------------------------------
__global__ void k_prep_gemm1(const int* __restrict__ ei1, const float* __restrict__ ew1,
                             const int* __restrict__ ei2, const float* __restrict__ ew2,
                             const float* __restrict__ x1, const float* __restrict__ x2,
                             const float* __restrict__ W1) {
    int tw = blockIdx.y;
    if (blockIdx.x < PREP_BLOCKS) {
        const int*   ei = tw ? ei2 : ei1;
        const float* ew = tw ? ew2 : ew1;
        int e = blockIdx.x * 256 + threadIdx.x;
        if (e < EE) {
            int d = ei[EE + e];
            float w = fmaxf(ew[e], 0.0f);          // relu(edge_weight)
            atomicAdd(&g_deg[tw][d], w);
            atomicAdd(&g_cnt[tw][d], 1);
        }
    } else {
        gemm_body<IN_DIM, O1>(tw ? x2 : x1, W1, g_h1[tw],
                              blockIdx.x - PREP_BLOCKS, 0, threadIdx.x);
    }
}

// phase 1: per-block exclusive partials + block sums
__global__ void k_scan1() {
    int tw   = blockIdx.y;
    int i    = blockIdx.x * SCAN_B + threadIdx.x;
    int lane = threadIdx.x & 31;
    int wid  = threadIdx.x >> 5;
    int c = (i < NN) ? g_cnt[tw][i] : 0;
    int v = c;
#pragma unroll
    for (int d = 1; d < 32; d <<= 1) {
        int t = __shfl_up_sync(0xffffffffu, v, d);
        if (lane >= d) v += t;
    }
    __shared__ int wsum[32];
    if (lane == 31) wsum[wid] = v;
    __syncthreads();
    if (wid == 0) {
        int w = wsum[lane];
#pragma unroll
        for (int d = 1; d < 32; d <<= 1) {
            int t = __shfl_up_sync(0xffffffffu, w, d);
            if (lane >= d) w += t;
        }
        wsum[lane] = w;
    }
    __syncthreads();
    int add = (wid > 0) ? wsum[wid - 1] : 0;
    if (i < NN) g_off[tw][i] = v + add - c;                 // exclusive within block
    if (threadIdx.x == SCAN_B - 1) g_blksum[tw][blockIdx.x] = wsum[31];
}

// phase 2+3 fused: each 256-node block adds its (single) block offset,
// computed by thread 0 as a short serial prefix over <=48 block sums;
// also inits g_cur and fuses dinv
__global__ void k_scan3() {
    int tw = blockIdx.y;
    __shared__ int s_off;
    if (threadIdx.x == 0) {
        int blk = (blockIdx.x * 256) / SCAN_B;
        int acc = 0;
        for (int b = 0; b < blk; b++) acc += g_blksum[tw][b];
        s_off = acc;
    }
    __syncthreads();
    int i = blockIdx.x * 256 + threadIdx.x;
    if (i < NN) {
        int o = g_off[tw][i] + s_off;
        g_off[tw][i] = o;
        g_cur[tw][i] = o;
        float d = g_deg[tw][i];
        g_dinv[tw][i] = (d > 0.0f) ? rsqrtf(fmaxf(d, 1e-30f)) : 0.0f;
    }
    if (i == 0) g_off[tw][NN] = EE;    // total count is always EE
}

__global__ void k_fill(const int* __restrict__ ei1, const float* __restrict__ ew1,
                       const int* __restrict__ ei2, const float* __restrict__ ew2) {
    int tw = blockIdx.y;
    const int*   ei = tw ? ei2 : ei1;
    const float* ew = tw ? ew2 : ew1;
    int e = blockIdx.x * blockDim.x + threadIdx.x;
    if (e < EE) {
        int s = ei[e], d = ei[EE + e];
        float w = fmaxf(ew[e], 0.0f);
        float nrm = g_dinv[tw][s] * w * g_dinv[tw][d];
        int pos = atomicAdd(&g_cur[tw][d], 1);
        g_edge[tw][pos] = make_int2(s, __float_as_int(nrm));
    }
}

__global__ void k_gemm2(const float* __restrict__ W2) {
    int tw = blockIdx.z;
    gemm_body<O1, O2>(g_z1[tw], W2, g_h2[tw],
                      blockIdx.x, blockIdx.y * 64, threadIdx.y * 16 + threadIdx.x);
}

// ---------------------------------------------------------------------------
// Aggregation 1: warp per node, gather-max over CSR edges (4x unrolled, MLP=4)
// ---------------------------------------------------------------------------
__global__ void k_aggr1(const float* __restrict__ b1) {
    int tw   = blockIdx.y;
    int warp = (blockIdx.x * blockDim.x + threadIdx.x) >> 5;
    int lane = threadIdx.x & 31;
    if (warp >= NN) return;
    const int2*  eg = g_edge[tw];
    const float* h  = g_h1[tw];
    int beg = g_off[tw][warp], end = g_off[tw][warp + 1];
    float dv = g_dinv[tw][warp];
    float sl = 2.0f * dv * dv;
    float2 self = *(const float2*)(h + (size_t)warp * O1 + lane * 2);
    float m0 = sl * self.x;
    float m1 = sl * self.y;
    int j = beg;
    for (; j + 4 <= end; j += 4) {
        int2 e0 = eg[j], e1 = eg[j + 1], e2 = eg[j + 2], e3 = eg[j + 3];
        float2 v0 = *(const float2*)(h + (size_t)e0.x * O1 + lane * 2);
        float2 v1 = *(const float2*)(h + (size_t)e1.x * O1 + lane * 2);
        float2 v2 = *(const float2*)(h + (size_t)e2.x * O1 + lane * 2);
        float2 v3 = *(const float2*)(h + (size_t)e3.x * O1 + lane * 2);
        float w0 = __int_as_float(e0.y), w1 = __int_as_float(e1.y);
        float w2 = __int_as_float(e2.y), w3 = __int_as_float(e3.y);
        m0 = fmaxf(m0, w0 * v0.x); m1 = fmaxf(m1, w0 * v0.y);
        m0 = fmaxf(m0, w1 * v1.x); m1 = fmaxf(m1, w1 * v1.y);
        m0 = fmaxf(m0, w2 * v2.x); m1 = fmaxf(m1, w2 * v2.y);
        m0 = fmaxf(m0, w3 * v3.x); m1 = fmaxf(m1, w3 * v3.y);
    }
    for (; j < end; j++) {
        int2 e = eg[j];
        float w = __int_as_float(e.y);
        float2 v = *(const float2*)(h + (size_t)e.x * O1 + lane * 2);
        m0 = fmaxf(m0, w * v.x);
        m1 = fmaxf(m1, w * v.y);
    }
    if (!isfinite(m0)) m0 = 0.0f;
    if (!isfinite(m1)) m1 = 0.0f;
    float2 bv = *(const float2*)(b1 + lane * 2);
    *(float2*)(g_z1[tw] + (size_t)warp * O1 + lane * 2) = make_float2(m0 + bv.x, m1 + bv.y);
}

// ---------------------------------------------------------------------------
// Aggregation 2: warp per node over 128 feats (float4/lane), 4x unrolled
// ---------------------------------------------------------------------------
__global__ void k_aggr2(const float* __restrict__ b2, float* __restrict__ out) {
    int tw   = blockIdx.y;
    int warp = (blockIdx.x * blockDim.x + threadIdx.x) >> 5;
    int lane = threadIdx.x & 31;
    if (warp >= NN) return;
    const int2*  eg = g_edge[tw];
    const float* h  = g_h2[tw];
    float* op = out + (size_t)tw * NN * O2;
    int beg = g_off[tw][warp], end = g_off[tw][warp + 1];
    float dv = g_dinv[tw][warp];
    float sl = 2.0f * dv * dv;
    float4 self = *(const float4*)(h + (size_t)warp * O2 + lane * 4);
    float m0 = sl * self.x, m1 = sl * self.y, m2 = sl * self.z, m3 = sl * self.w;
    int j = beg;
    for (; j + 4 <= end; j += 4) {
        int2 e0 = eg[j], e1 = eg[j + 1], e2 = eg[j + 2], e3 = eg[j + 3];
        float4 v0 = *(const float4*)(h + (size_t)e0.x * O2 + lane * 4);
        float4 v1 = *(const float4*)(h + (size_t)e1.x * O2 + lane * 4);
        float4 v2 = *(const float4*)(h + (size_t)e2.x * O2 + lane * 4);
        float4 v3 = *(const float4*)(h + (size_t)e3.x * O2 + lane * 4);
        float w0 = __int_as_float(e0.y), w1 = __int_as_float(e1.y);
        float w2 = __int_as_float(e2.y), w3 = __int_as_float(e3.y);
        m0 = fmaxf(m0, w0 * v0.x); m1 = fmaxf(m1, w0 * v0.y);
        m2 = fmaxf(m2, w0 * v0.z); m3 = fmaxf(m3, w0 * v0.w);
        m0 = fmaxf(m0, w1 * v1.x); m1 = fmaxf(m1, w1 * v1.y);
        m2 = fmaxf(m2, w1 * v1.z); m3 = fmaxf(m3, w1 * v1.w);
        m0 = fmaxf(m0, w2 * v2.x); m1 = fmaxf(m1, w2 * v2.y);
        m2 = fmaxf(m2, w2 * v2.z); m3 = fmaxf(m3, w2 * v2.w);
        m0 = fmaxf(m0, w3 * v3.x); m1 = fmaxf(m1, w3 * v3.y);
        m2 = fmaxf(m2, w3 * v3.z); m3 = fmaxf(m3, w3 * v3.w);
    }
    for (; j < end; j++) {
        int2 e = eg[j];
        float w = __int_as_float(e.y);
        float4 v = *(const float4*)(h + (size_t)e.x * O2 + lane * 4);
        m0 = fmaxf(m0, w * v.x); m1 = fmaxf(m1, w * v.y);
        m2 = fmaxf(m2, w * v.z); m3 = fmaxf(m3, w * v.w);
    }
    if (!isfinite(m0)) m0 = 0.0f;
    if (!isfinite(m1)) m1 = 0.0f;
    if (!isfinite(m2)) m2 = 0.0f;
    if (!isfinite(m3)) m3 = 0.0f;
    float4 bv = *(const float4*)(b2 + lane * 4);
    *(float4*)(op + (size_t)warp * O2 + lane * 4) =
        make_float4(m0 + bv.x, m1 + bv.y, m2 + bv.z, m3 + bv.w);
}

// ---------------------------------------------------------------------------
// launch
// ---------------------------------------------------------------------------
extern "C" void kernel_launch(void* const* d_in, const int* in_sizes, int n_in,
                              void* d_out, int out_size) {
    const float* x1  = (const float*)d_in[0];
    const int*   ei1 = (const int*)  d_in[1];
    const float* ew1 = (const float*)d_in[2];
    const float* x2  = (const float*)d_in[3];
    const int*   ei2 = (const int*)  d_in[4];
    const float* ew2 = (const float*)d_in[5];
    const float* W1  = (const float*)d_in[6];
    const float* b1  = (const float*)d_in[7];
    const float* W2  = (const float*)d_in[8];
    const float* b2  = (const float*)d_in[9];
    float* out = (float*)d_out;

    const int TB = 256;
    k_init      <<<dim3((NN + TB - 1) / TB, 2), TB>>>();
    k_prep_gemm1<<<dim3(PREP_BLOCKS + G1_BLOCKS, 2), TB>>>(ei1, ew1, ei2, ew2, x1, x2, W1);
    k_scan1     <<<dim3(NBLK, 2), SCAN_B>>>();
    k_scan3     <<<dim3((NN + TB - 1) / TB, 2), TB>>>();
    k_fill      <<<dim3((EE + TB - 1) / TB, 2), TB>>>(ei1, ew1, ei2, ew2);

    k_aggr1<<<dim3((NN * 32 + TB - 1) / TB, 2), TB>>>(b1);
    dim3 gblk(16, 16);
    k_gemm2<<<dim3(G1_BLOCKS, 2, 2), gblk>>>(W2);
    k_aggr2<<<dim3((NN * 32 + TB - 1) / TB, 2), TB>>>(b2, out);
}

// round 6
// speedup vs baseline: 4.0462x; 1.0238x over previous
#include <cuda_runtime.h>
#include <cuda_fp16.h>
#include <math.h>

#define NN   50000
#define EE   800000
#define IN_DIM 128
#define O1   64
#define O2   128

#define SCAN_B 1024
#define NBLK   ((NN + SCAN_B - 1) / SCAN_B)   // 49

#define PREP_BLOCKS ((EE + 255) / 256)        // 3125
#define G1_BLOCKS   ((NN + 63) / 64)          // 782

// Scratch (device globals — no allocation allowed). Index 0/1 = tower.
__device__ float g_deg [2][NN];
__device__ float g_dinv[2][NN];
__device__ int   g_cnt [2][NN];
__device__ int   g_off [2][NN + 1];
__device__ int   g_cur [2][NN];
__device__ int   g_blksum[2][64];
__device__ int2  g_edge[2][EE];          // (src, float-bits of norm)
__device__ float g_h1[2][NN * O1];
__device__ float g_z1[2][NN * O1];
__device__ __half g_h2h[2][NN * O2];     // layer-2 hidden in fp16 (gather-bound)

// ---------------------------------------------------------------------------
// packed fp32x2 FMA (sm_103a FFMA2)
// ---------------------------------------------------------------------------
__device__ __forceinline__ void ffma2(float2& acc, float2 a, float2 w) {
    unsigned long long ac, av, wv;
    ac = *(unsigned long long*)&acc;
    av = *(unsigned long long*)&a;
    wv = *(unsigned long long*)&w;
    asm("fma.rn.f32x2 %0, %1, %2, %0;" : "+l"(ac) : "l"(av), "l"(wv));
    acc = *(float2*)&ac;
}

// ---------------------------------------------------------------------------
// Register-tiled GEMM body: C[64-row tile, 64-col tile] = A[N,K] @ W[K,OC]
// 256 flat threads; each thread 4 rows x 4 cols; k paired for fma.rn.f32x2
// HALF_OUT: write fp16 instead of fp32
// ---------------------------------------------------------------------------
template<int K, int OC, bool HALF_OUT>
__device__ __forceinline__ void gemm_body(const float* __restrict__ A,
                                          const float* __restrict__ W,
                                          void* __restrict__ C,
                                          int rowBlk, int colBase, int tid) {
    __shared__ float2 Wp[(K / 2) * 64];   // Wp[kp*64 + c] = (W[2kp][c], W[2kp+1][c])
    int tx = tid & 15;                    // cols
    int ty = tid >> 4;                    // rows
    for (int idx = tid; idx < (K / 2) * 64; idx += 256) {
        int kp = idx >> 6, c = idx & 63;
        Wp[idx] = make_float2(W[(2 * kp)     * OC + colBase + c],
                              W[(2 * kp + 1) * OC + colBase + c]);
    }
    __syncthreads();

    int r0 = rowBlk * 64 + ty * 4;
    int c0 = tx * 4;
    float2 acc[4][4];
#pragma unroll
    for (int i = 0; i < 4; i++)
#pragma unroll
        for (int j = 0; j < 4; j++) acc[i][j] = make_float2(0.0f, 0.0f);

#pragma unroll 4
    for (int kk = 0; kk < K; kk += 4) {
        float4 a[4];
#pragma unroll
        for (int i = 0; i < 4; i++) {
            int r = r0 + i;
            a[i] = (r < NN) ? *(const float4*)(A + (size_t)r * K + kk)
                            : make_float4(0.0f, 0.0f, 0.0f, 0.0f);
        }
#pragma unroll
        for (int kp = 0; kp < 2; kp++) {
            const float2* wrow = Wp + ((kk >> 1) + kp) * 64 + c0;
            float4 wA = *(const float4*)(wrow);       // cols c0, c0+1
            float4 wB = *(const float4*)(wrow + 2);   // cols c0+2, c0+3
            float2 w0 = make_float2(wA.x, wA.y);
            float2 w1 = make_float2(wA.z, wA.w);
            float2 w2 = make_float2(wB.x, wB.y);
            float2 w3 = make_float2(wB.z, wB.w);
#pragma unroll
            for (int i = 0; i < 4; i++) {
                float2 ap = kp ? make_float2(a[i].z, a[i].w)
                               : make_float2(a[i].x, a[i].y);
                ffma2(acc[i][0], ap, w0);
                ffma2(acc[i][1], ap, w1);
                ffma2(acc[i][2], ap, w2);
                ffma2(acc[i][3], ap, w3);
            }
        }
    }
#pragma unroll
    for (int i = 0; i < 4; i++) {
        int r = r0 + i;
        if (r < NN) {
            float4 o;
            o.x = acc[i][0].x + acc[i][0].y;
            o.y = acc[i][1].x + acc[i][1].y;
            o.z = acc[i][2].x + acc[i][2].y;
            o.w = acc[i][3].x + acc[i][3].y;
            if (HALF_OUT) {
                __half2 p0 = __floats2half2_rn(o.x, o.y);
                __half2 p1 = __floats2half2_rn(o.z, o.w);
                uint2 pk;
                pk.x = *(unsigned*)&p0;
                pk.y = *(unsigned*)&p1;
                *(uint2*)((__half*)C + (size_t)r * OC + colBase + c0) = pk;
            } else {
                *(float4*)((float*)C + (size_t)r * OC + colBase + c0) = o;
            }
        }
    }
}

// ---------------------------------------------------------------------------
// init
// ---------------------------------------------------------------------------
__global__ void k_init() {
    int tw = blockIdx.y;
    int i = blockIdx.x * blockDim.x + threadIdx.x;
    if (i < NN) {
        g_deg[tw][i] = 2.0f;   // improved=True self-loop fill
        g_cnt[tw][i] = 0;
    }
}

// ---------------------------------------------------------------------------
// fused: deg/count atomics (blocks [0,PREP_BLOCKS)) | GEMM1 (the rest)
// ---------------------------------------------------------------------------
__global__ void k_prep_gemm1(const int* __restrict__ ei1, const float* __restrict__ ew1,
                             const int* __restrict__ ei2, const float* __restrict__ ew2,
                             const float* __restrict__ x1, const float* __restrict__ x2,
                             const float* __restrict__ W1) {
    int tw = blockIdx.y;
    if (blockIdx.x < PREP_BLOCKS) {
        const int*   ei = tw ? ei2 : ei1;
        const float* ew = tw ? ew2 : ew1;
        int e = blockIdx.x * 256 + threadIdx.x;
        if (e < EE) {
            int d = ei[EE + e];
            float w = fmaxf(ew[e], 0.0f);          // relu(edge_weight)
            atomicAdd(&g_deg[tw][d], w);
            atomicAdd(&g_cnt[tw][d], 1);
        }
    } else {
        gemm_body<IN_DIM, O1, false>(tw ? x2 : x1, W1, g_h1[tw],
                                     blockIdx.x - PREP_BLOCKS, 0, threadIdx.x);
    }
}

// phase 1: per-block exclusive partials + block sums
__global__ void k_scan1() {
    int tw   = blockIdx.y;
    int i    = blockIdx.x * SCAN_B + threadIdx.x;
    int lane = threadIdx.x & 31;
    int wid  = threadIdx.x >> 5;
    int c = (i < NN) ? g_cnt[tw][i] : 0;
    int v = c;
#pragma unroll
    for (int d = 1; d < 32; d <<= 1) {
        int t = __shfl_up_sync(0xffffffffu, v, d);
        if (lane >= d) v += t;
    }
    __shared__ int wsum[32];
    if (lane == 31) wsum[wid] = v;
    __syncthreads();
    if (wid == 0) {
        int w = wsum[lane];
#pragma unroll
        for (int d = 1; d < 32; d <<= 1) {
            int t = __shfl_up_sync(0xffffffffu, w, d);
            if (lane >= d) w += t;
        }
        wsum[lane] = w;
    }
    __syncthreads();
    int add = (wid > 0) ? wsum[wid - 1] : 0;
    if (i < NN) g_off[tw][i] = v + add - c;                 // exclusive within block
    if (threadIdx.x == SCAN_B - 1) g_blksum[tw][blockIdx.x] = wsum[31];
}

// phase 2+3 fused: per-256-node block offset via short serial prefix; + dinv
__global__ void k_scan3() {
    int tw = blockIdx.y;
    __shared__ int s_off;
    if (threadIdx.x == 0) {
        int blk = (blockIdx.x * 256) / SCAN_B;
        int acc = 0;
        for (int b = 0; b < blk; b++) acc += g_blksum[tw][b];
        s_off = acc;
    }
    __syncthreads();
    int i = blockIdx.x * 256 + threadIdx.x;
    if (i < NN) {
        int o = g_off[tw][i] + s_off;
        g_off[tw][i] = o;
        g_cur[tw][i] = o;
        float d = g_deg[tw][i];
        g_dinv[tw][i] = (d > 0.0f) ? rsqrtf(fmaxf(d, 1e-30f)) : 0.0f;
    }
    if (i == 0) g_off[tw][NN] = EE;    // total count is always EE
}

__global__ void k_fill(const int* __restrict__ ei1, const float* __restrict__ ew1,
                       const int* __restrict__ ei2, const float* __restrict__ ew2) {
    int tw = blockIdx.y;
    const int*   ei = tw ? ei2 : ei1;
    const float* ew = tw ? ew2 : ew1;
    int e = blockIdx.x * blockDim.x + threadIdx.x;
    if (e < EE) {
        int s = ei[e], d = ei[EE + e];
        float w = fmaxf(ew[e], 0.0f);
        float nrm = g_dinv[tw][s] * w * g_dinv[tw][d];
        int pos = atomicAdd(&g_cur[tw][d], 1);
        g_edge[tw][pos] = make_int2(s, __float_as_int(nrm));
    }
}

__global__ void k_gemm2(const float* __restrict__ W2) {
    int tw = blockIdx.z;
    gemm_body<O1, O2, true>(g_z1[tw], W2, g_h2h[tw],
                            blockIdx.x, blockIdx.y * 64, threadIdx.y * 16 + threadIdx.x);
}

// ---------------------------------------------------------------------------
// Aggregation 1: warp per node, gather-max over CSR edges (4x unrolled, MLP=4)
// ---------------------------------------------------------------------------
__global__ void k_aggr1(const float* __restrict__ b1) {
    int tw   = blockIdx.y;
    int warp = (blockIdx.x * blockDim.x + threadIdx.x) >> 5;
    int lane = threadIdx.x & 31;
    if (warp >= NN) return;
    const int2*  eg = g_edge[tw];
    const float* h  = g_h1[tw];
    int beg = g_off[tw][warp], end = g_off[tw][warp + 1];
    float dv = g_dinv[tw][warp];
    float sl = 2.0f * dv * dv;
    float2 self = *(const float2*)(h + (size_t)warp * O1 + lane * 2);
    float m0 = sl * self.x;
    float m1 = sl * self.y;
    int j = beg;
    for (; j + 4 <= end; j += 4) {
        int2 e0 = eg[j], e1 = eg[j + 1], e2 = eg[j + 2], e3 = eg[j + 3];
        float2 v0 = *(const float2*)(h + (size_t)e0.x * O1 + lane * 2);
        float2 v1 = *(const float2*)(h + (size_t)e1.x * O1 + lane * 2);
        float2 v2 = *(const float2*)(h + (size_t)e2.x * O1 + lane * 2);
        float2 v3 = *(const float2*)(h + (size_t)e3.x * O1 + lane * 2);
        float w0 = __int_as_float(e0.y), w1 = __int_as_float(e1.y);
        float w2 = __int_as_float(e2.y), w3 = __int_as_float(e3.y);
        m0 = fmaxf(m0, w0 * v0.x); m1 = fmaxf(m1, w0 * v0.y);
        m0 = fmaxf(m0, w1 * v1.x); m1 = fmaxf(m1, w1 * v1.y);
        m0 = fmaxf(m0, w2 * v2.x); m1 = fmaxf(m1, w2 * v2.y);
        m0 = fmaxf(m0, w3 * v3.x); m1 = fmaxf(m1, w3 * v3.y);
    }
    for (; j < end; j++) {
        int2 e = eg[j];
        float w = __int_as_float(e.y);
        float2 v = *(const float2*)(h + (size_t)e.x * O1 + lane * 2);
        m0 = fmaxf(m0, w * v.x);
        m1 = fmaxf(m1, w * v.y);
    }
    if (!isfinite(m0)) m0 = 0.0f;
    if (!isfinite(m1)) m1 = 0.0f;
    float2 bv = *(const float2*)(b1 + lane * 2);
    *(float2*)(g_z1[tw] + (size_t)warp * O1 + lane * 2) = make_float2(m0 + bv.x, m1 + bv.y);
}

// ---------------------------------------------------------------------------
// Aggregation 2: warp per node over 128 fp16 feats (8B/lane), 4x unrolled
// ---------------------------------------------------------------------------
__device__ __forceinline__ void max4_half(float& m0, float& m1, float& m2, float& m3,
                                          uint2 pk, float w) {
    __half2 p0 = *(__half2*)&pk.x;
    __half2 p1 = *(__half2*)&pk.y;
    float2 f0 = __half22float2(p0);
    float2 f1 = __half22float2(p1);
    m0 = fmaxf(m0, w * f0.x); m1 = fmaxf(m1, w * f0.y);
    m2 = fmaxf(m2, w * f1.x); m3 = fmaxf(m3, w * f1.y);
}

__global__ void k_aggr2(const float* __restrict__ b2, float* __restrict__ out) {
    int tw   = blockIdx.y;
    int warp = (blockIdx.x * blockDim.x + threadIdx.x) >> 5;
    int lane = threadIdx.x & 31;
    if (warp >= NN) return;
    const int2*   eg = g_edge[tw];
    const __half* h  = g_h2h[tw];
    float* op = out + (size_t)tw * NN * O2;
    int beg = g_off[tw][warp], end = g_off[tw][warp + 1];
    float dv = g_dinv[tw][warp];
    float sl = 2.0f * dv * dv;
    uint2 selfpk = *(const uint2*)(h + (size_t)warp * O2 + lane * 4);
    float m0 = -1e30f, m1 = -1e30f, m2 = -1e30f, m3 = -1e30f;
    max4_half(m0, m1, m2, m3, selfpk, sl);
    int j = beg;
    for (; j + 4 <= end; j += 4) {
        int2 e0 = eg[j], e1 = eg[j + 1], e2 = eg[j + 2], e3 = eg[j + 3];
        uint2 v0 = *(const uint2*)(h + (size_t)e0.x * O2 + lane * 4);
        uint2 v1 = *(const uint2*)(h + (size_t)e1.x * O2 + lane * 4);
        uint2 v2 = *(const uint2*)(h + (size_t)e2.x * O2 + lane * 4);
        uint2 v3 = *(const uint2*)(h + (size_t)e3.x * O2 + lane * 4);
        max4_half(m0, m1, m2, m3, v0, __int_as_float(e0.y));
        max4_half(m0, m1, m2, m3, v1, __int_as_float(e1.y));
        max4_half(m0, m1, m2, m3, v2, __int_as_float(e2.y));
        max4_half(m0, m1, m2, m3, v3, __int_as_float(e3.y));
    }
    for (; j < end; j++) {
        int2 e = eg[j];
        uint2 v = *(const uint2*)(h + (size_t)e.x * O2 + lane * 4);
        max4_half(m0, m1, m2, m3, v, __int_as_float(e.y));
    }
    if (!isfinite(m0)) m0 = 0.0f;
    if (!isfinite(m1)) m1 = 0.0f;
    if (!isfinite(m2)) m2 = 0.0f;
    if (!isfinite(m3)) m3 = 0.0f;
    float4 bv = *(const float4*)(b2 + lane * 4);
    *(float4*)(op + (size_t)warp * O2 + lane * 4) =
        make_float4(m0 + bv.x, m1 + bv.y, m2 + bv.z, m3 + bv.w);
}

// ---------------------------------------------------------------------------
// launch
// ---------------------------------------------------------------------------
extern "C" void kernel_launch(void* const* d_in, const int* in_sizes, int n_in,
                              void* d_out, int out_size) {
    const float* x1  = (const float*)d_in[0];
    const int*   ei1 = (const int*)  d_in[1];
    const float* ew1 = (const float*)d_in[2];
    const float* x2  = (const float*)d_in[3];
    const int*   ei2 = (const int*)  d_in[4];
    const float* ew2 = (const float*)d_in[5];
    const float* W1  = (const float*)d_in[6];
    const float* b1  = (const float*)d_in[7];
    const float* W2  = (const float*)d_in[8];
    const float* b2  = (const float*)d_in[9];
    float* out = (float*)d_out;

    const int TB = 256;
    k_init      <<<dim3((NN + TB - 1) / TB, 2), TB>>>();
    k_prep_gemm1<<<dim3(PREP_BLOCKS + G1_BLOCKS, 2), TB>>>(ei1, ew1, ei2, ew2, x1, x2, W1);
    k_scan1     <<<dim3(NBLK, 2), SCAN_B>>>();
    k_scan3     <<<dim3((NN + TB - 1) / TB, 2), TB>>>();
    k_fill      <<<dim3((EE + TB - 1) / TB, 2), TB>>>(ei1, ew1, ei2, ew2);

    k_aggr1<<<dim3((NN * 32 + TB - 1) / TB, 2), TB>>>(b1);
    dim3 gblk(16, 16);
    k_gemm2<<<dim3(G1_BLOCKS, 2, 2), gblk>>>(W2);
    k_aggr2<<<dim3((NN * 32 + TB - 1) / TB, 2), TB>>>(b2, out);
}

// round 7
// speedup vs baseline: 4.2815x; 1.0582x over previous
#include <cuda_runtime.h>
#include <cuda_fp16.h>
#include <math.h>

#define NN   50000
#define EE   800000
#define IN_DIM 128
#define O1   64
#define O2   128

#define SCAN_B 1024
#define NBLK   ((NN + SCAN_B - 1) / SCAN_B)   // 49

#define PREP_BLOCKS ((EE + 255) / 256)        // 3125
#define G1_BLOCKS   ((NN + 63) / 64)          // 782

#define DEG_SCALE 1048576.0f                  // 2^20 fixed point for edge-weight sums

// Scratch (device globals — no allocation allowed). Index 0/1 = tower.
__device__ unsigned long long g_dc[2][NN];    // hi32 = count, lo32 = fixedpoint sum(relu(w))
__device__ unsigned long long g_lk[2][64];    // lookback: hi32 flag (0/1/2), lo32 value
__device__ float  g_dinv[2][NN];
__device__ int    g_off [2][NN];              // exclusive offsets; mutated by k_fill into ends
__device__ int2   g_edge[2][EE];              // (src, float-bits of norm)
__device__ __half g_h1h[2][NN * O1];          // layer-1 hidden fp16 (gather-bound)
__device__ float  g_z1 [2][NN * O1];
__device__ __half g_h2h[2][NN * O2];          // layer-2 hidden fp16 (gather-bound)

// ---------------------------------------------------------------------------
// packed fp32x2 FMA (sm_103a FFMA2)
// ---------------------------------------------------------------------------
__device__ __forceinline__ void ffma2(float2& acc, float2 a, float2 w) {
    unsigned long long ac, av, wv;
    ac = *(unsigned long long*)&acc;
    av = *(unsigned long long*)&a;
    wv = *(unsigned long long*)&w;
    asm("fma.rn.f32x2 %0, %1, %2, %0;" : "+l"(ac) : "l"(av), "l"(wv));
    acc = *(float2*)&ac;
}

// ---------------------------------------------------------------------------
// Register-tiled GEMM body: C[64-row tile, 64-col tile] = A[N,K] @ W[K,OC]
// 256 flat threads; each thread 4 rows x 4 cols; k paired for fma.rn.f32x2
// Output written as fp16 (4 halves = uint2 per thread-row)
// ---------------------------------------------------------------------------
template<int K, int OC>
__device__ __forceinline__ void gemm_body(const float* __restrict__ A,
                                          const float* __restrict__ W,
                                          __half* __restrict__ C,
                                          int rowBlk, int colBase, int tid) {
    __shared__ float2 Wp[(K / 2) * 64];   // Wp[kp*64 + c] = (W[2kp][c], W[2kp+1][c])
    int tx = tid & 15;                    // cols
    int ty = tid >> 4;                    // rows
    for (int idx = tid; idx < (K / 2) * 64; idx += 256) {
        int kp = idx >> 6, c = idx & 63;
        Wp[idx] = make_float2(W[(2 * kp)     * OC + colBase + c],
                              W[(2 * kp + 1) * OC + colBase + c]);
    }
    __syncthreads();

    int r0 = rowBlk * 64 + ty * 4;
    int c0 = tx * 4;
    float2 acc[4][4];
#pragma unroll
    for (int i = 0; i < 4; i++)
#pragma unroll
        for (int j = 0; j < 4; j++) acc[i][j] = make_float2(0.0f, 0.0f);

#pragma unroll 4
    for (int kk = 0; kk < K; kk += 4) {
        float4 a[4];
#pragma unroll
        for (int i = 0; i < 4; i++) {
            int r = r0 + i;
            a[i] = (r < NN) ? *(const float4*)(A + (size_t)r * K + kk)
                            : make_float4(0.0f, 0.0f, 0.0f, 0.0f);
        }
#pragma unroll
        for (int kp = 0; kp < 2; kp++) {
            const float2* wrow = Wp + ((kk >> 1) + kp) * 64 + c0;
            float4 wA = *(const float4*)(wrow);       // cols c0, c0+1
            float4 wB = *(const float4*)(wrow + 2);   // cols c0+2, c0+3
            float2 w0 = make_float2(wA.x, wA.y);
            float2 w1 = make_float2(wA.z, wA.w);
            float2 w2 = make_float2(wB.x, wB.y);
            float2 w3 = make_float2(wB.z, wB.w);
#pragma unroll
            for (int i = 0; i < 4; i++) {
                float2 ap = kp ? make_float2(a[i].z, a[i].w)
                               : make_float2(a[i].x, a[i].y);
                ffma2(acc[i][0], ap, w0);
                ffma2(acc[i][1], ap, w1);
                ffma2(acc[i][2], ap, w2);
                ffma2(acc[i][3], ap, w3);
            }
        }
    }
#pragma unroll
    for (int i = 0; i < 4; i++) {
        int r = r0 + i;
        if (r < NN) {
            __half2 p0 = __floats2half2_rn(acc[i][0].x + acc[i][0].y,
                                           acc[i][1].x + acc[i][1].y);
            __half2 p1 = __floats2half2_rn(acc[i][2].x + acc[i][2].y,
                                           acc[i][3].x + acc[i][3].y);
            uint2 pk;
            pk.x = *(unsigned*)&p0;
            pk.y = *(unsigned*)&p1;
            *(uint2*)(C + (size_t)r * OC + colBase + c0) = pk;
        }
    }
}

// ---------------------------------------------------------------------------
// init: zero packed deg/count + lookback flags
// ---------------------------------------------------------------------------
__global__ void k_init() {
    int tw = blockIdx.y;
    int i = blockIdx.x * blockDim.x + threadIdx.x;
    if (i < NN) g_dc[tw][i] = 0ULL;
    if (i < 64) g_lk[tw][i] = 0ULL;
}

// ---------------------------------------------------------------------------
// fused: packed deg/count atomics (blocks [0,PREP_BLOCKS)) | GEMM1 (the rest)
// ---------------------------------------------------------------------------
__global__ void k_prep_gemm1(const int* __restrict__ ei1, const float* __restrict__ ew1,
                             const int* __restrict__ ei2, const float* __restrict__ ew2,
                             const float* __restrict__ x1, const float* __restrict__ x2,
                             const float* __restrict__ W1) {
    int tw = blockIdx.y;
    if (blockIdx.x < PREP_BLOCKS) {
        const int*   ei = tw ? ei2 : ei1;
        const float* ew = tw ? ew2 : ew1;
        int e = blockIdx.x * 256 + threadIdx.x;
        if (e < EE) {
            int d = ei[EE + e];
            float w = fmaxf(ew[e], 0.0f);          // relu(edge_weight)
            unsigned long long pk =
                (1ULL << 32) | (unsigned long long)__float2uint_rn(w * DEG_SCALE);
            atomicAdd(&g_dc[tw][d], pk);
        }
    } else {
        gemm_body<IN_DIM, O1>(tw ? x2 : x1, W1, g_h1h[tw],
                              blockIdx.x - PREP_BLOCKS, 0, threadIdx.x);
    }
}

// ---------------------------------------------------------------------------
// single-pass scan (decoupled lookback) + dinv. grid (NBLK,2) x 1024 threads
// ---------------------------------------------------------------------------
__global__ void k_scan() {
    int tw   = blockIdx.y;
    int b    = blockIdx.x;
    int i    = b * SCAN_B + threadIdx.x;
    int lane = threadIdx.x & 31;
    int wid  = threadIdx.x >> 5;
    unsigned long long dc = (i < NN) ? g_dc[tw][i] : 0ULL;
    int c = (int)(dc >> 32);
    int v = c;
#pragma unroll
    for (int d = 1; d < 32; d <<= 1) {
        int t = __shfl_up_sync(0xffffffffu, v, d);
        if (lane >= d) v += t;
    }
    __shared__ int wsum[32];
    if (lane == 31) wsum[wid] = v;
    __syncthreads();
    if (wid == 0) {
        int w = wsum[lane];
#pragma unroll
        for (int d = 1; d < 32; d <<= 1) {
            int t = __shfl_up_sync(0xffffffffu, w, d);
            if (lane >= d) w += t;
        }
        wsum[lane] = w;
    }
    __syncthreads();
    int add = (wid > 0) ? wsum[wid - 1] : 0;
    int incl = v + add;                   // inclusive within block
    int total = wsum[31];

    __shared__ int s_exc;
    if (threadIdx.x == 0) {
        // publish aggregate (or inclusive for block 0)
        unsigned long long flag = (b == 0) ? 2ULL : 1ULL;
        atomicExch(&g_lk[tw][b], (flag << 32) | (unsigned)total);
        int exc = 0;
        if (b > 0) {
            int p = b - 1;
            while (true) {
                unsigned long long pv = *((volatile unsigned long long*)&g_lk[tw][p]);
                unsigned f = (unsigned)(pv >> 32);
                if (f == 2u) { exc += (int)(unsigned)pv; break; }
                if (f == 1u) { exc += (int)(unsigned)pv; p--; }
            }
            atomicExch(&g_lk[tw][b], (2ULL << 32) | (unsigned)(total + exc));
        }
        s_exc = exc;
    }
    __syncthreads();
    if (i < NN) {
        g_off[tw][i] = s_exc + incl - c;   // exclusive global offset
        float deg = 2.0f + (float)(unsigned)dc * (1.0f / DEG_SCALE);
        g_dinv[tw][i] = rsqrtf(deg);
    }
}

// ---------------------------------------------------------------------------
// fill: bump g_off[d] directly (afterwards g_off[d] = end of bucket d)
// ---------------------------------------------------------------------------
__global__ void k_fill(const int* __restrict__ ei1, const float* __restrict__ ew1,
                       const int* __restrict__ ei2, const float* __restrict__ ew2) {
    int tw = blockIdx.y;
    const int*   ei = tw ? ei2 : ei1;
    const float* ew = tw ? ew2 : ew1;
    int e = blockIdx.x * blockDim.x + threadIdx.x;
    if (e < EE) {
        int s = ei[e], d = ei[EE + e];
        float w = fmaxf(ew[e], 0.0f);
        float nrm = g_dinv[tw][s] * w * g_dinv[tw][d];
        int pos = atomicAdd(&g_off[tw][d], 1);
        g_edge[tw][pos] = make_int2(s, __float_as_int(nrm));
    }
}

__global__ void k_gemm2(const float* __restrict__ W2) {
    int tw = blockIdx.z;
    gemm_body<O1, O2>(g_z1[tw], W2, g_h2h[tw],
                      blockIdx.x, blockIdx.y * 64, threadIdx.y * 16 + threadIdx.x);
}

// ---------------------------------------------------------------------------
// Aggregation 1: warp per node, fp16 gather-max over CSR edges (4x unrolled)
// offsets are post-fill: beg = off[d-1], end = off[d]
// ---------------------------------------------------------------------------
__device__ __forceinline__ void max2_half(float& m0, float& m1, unsigned pk, float w) {
    float2 f = __half22float2(*(__half2*)&pk);
    m0 = fmaxf(m0, w * f.x);
    m1 = fmaxf(m1, w * f.y);
}

__global__ void k_aggr1(const float* __restrict__ b1) {
    int tw   = blockIdx.y;
    int warp = (blockIdx.x * blockDim.x + threadIdx.x) >> 5;
    int lane = threadIdx.x & 31;
    if (warp >= NN) return;
    const int2*   eg = g_edge[tw];
    const __half* h  = g_h1h[tw];
    int beg = (warp > 0) ? g_off[tw][warp - 1] : 0;
    int end = g_off[tw][warp];
    float dv = g_dinv[tw][warp];
    float sl = 2.0f * dv * dv;
    unsigned selfpk = *(const unsigned*)(h + (size_t)warp * O1 + lane * 2);
    float m0 = -1e30f, m1 = -1e30f;
    max2_half(m0, m1, selfpk, sl);
    int j = beg;
    for (; j + 4 <= end; j += 4) {
        int2 e0 = eg[j], e1 = eg[j + 1], e2 = eg[j + 2], e3 = eg[j + 3];
        unsigned v0 = *(const unsigned*)(h + (size_t)e0.x * O1 + lane * 2);
        unsigned v1 = *(const unsigned*)(h + (size_t)e1.x * O1 + lane * 2);
        unsigned v2 = *(const unsigned*)(h + (size_t)e2.x * O1 + lane * 2);
        unsigned v3 = *(const unsigned*)(h + (size_t)e3.x * O1 + lane * 2);
        max2_half(m0, m1, v0, __int_as_float(e0.y));
        max2_half(m0, m1, v1, __int_as_float(e1.y));
        max2_half(m0, m1, v2, __int_as_float(e2.y));
        max2_half(m0, m1, v3, __int_as_float(e3.y));
    }
    for (; j < end; j++) {
        int2 e = eg[j];
        unsigned v = *(const unsigned*)(h + (size_t)e.x * O1 + lane * 2);
        max2_half(m0, m1, v, __int_as_float(e.y));
    }
    if (!isfinite(m0)) m0 = 0.0f;
    if (!isfinite(m1)) m1 = 0.0f;
    float2 bv = *(const float2*)(b1 + lane * 2);
    *(float2*)(g_z1[tw] + (size_t)warp * O1 + lane * 2) = make_float2(m0 + bv.x, m1 + bv.y);
}

// ---------------------------------------------------------------------------
// Aggregation 2: warp per node over 128 fp16 feats (8B/lane), 4x unrolled
// ---------------------------------------------------------------------------
__device__ __forceinline__ void max4_half(float& m0, float& m1, float& m2, float& m3,
                                          uint2 pk, float w) {
    float2 f0 = __half22float2(*(__half2*)&pk.x);
    float2 f1 = __half22float2(*(__half2*)&pk.y);
    m0 = fmaxf(m0, w * f0.x); m1 = fmaxf(m1, w * f0.y);
    m2 = fmaxf(m2, w * f1.x); m3 = fmaxf(m3, w * f1.y);
}

__global__ void k_aggr2(const float* __restrict__ b2, float* __restrict__ out) {
    int tw   = blockIdx.y;
    int warp = (blockIdx.x * blockDim.x + threadIdx.x) >> 5;
    int lane = threadIdx.x & 31;
    if (warp >= NN) return;
    const int2*   eg = g_edge[tw];
    const __half* h  = g_h2h[tw];
    float* op = out + (size_t)tw * NN * O2;
    int beg = (warp > 0) ? g_off[tw][warp - 1] : 0;
    int end = g_off[tw][warp];
    float dv = g_dinv[tw][warp];
    float sl = 2.0f * dv * dv;
    uint2 selfpk = *(const uint2*)(h + (size_t)warp * O2 + lane * 4);
    float m0 = -1e30f, m1 = -1e30f, m2 = -1e30f, m3 = -1e30f;
    max4_half(m0, m1, m2, m3, selfpk, sl);
    int j = beg;
    for (; j + 4 <= end; j += 4) {
        int2 e0 = eg[j], e1 = eg[j + 1], e2 = eg[j + 2], e3 = eg[j + 3];
        uint2 v0 = *(const uint2*)(h + (size_t)e0.x * O2 + lane * 4);
        uint2 v1 = *(const uint2*)(h + (size_t)e1.x * O2 + lane * 4);
        uint2 v2 = *(const uint2*)(h + (size_t)e2.x * O2 + lane * 4);
        uint2 v3 = *(const uint2*)(h + (size_t)e3.x * O2 + lane * 4);
        max4_half(m0, m1, m2, m3, v0, __int_as_float(e0.y));
        max4_half(m0, m1, m2, m3, v1, __int_as_float(e1.y));
        max4_half(m0, m1, m2, m3, v2, __int_as_float(e2.y));
        max4_half(m0, m1, m2, m3, v3, __int_as_float(e3.y));
    }
    for (; j < end; j++) {
        int2 e = eg[j];
        uint2 v = *(const uint2*)(h + (size_t)e.x * O2 + lane * 4);
        max4_half(m0, m1, m2, m3, v, __int_as_float(e.y));
    }
    if (!isfinite(m0)) m0 = 0.0f;
    if (!isfinite(m1)) m1 = 0.0f;
    if (!isfinite(m2)) m2 = 0.0f;
    if (!isfinite(m3)) m3 = 0.0f;
    float4 bv = *(const float4*)(b2 + lane * 4);
    *(float4*)(op + (size_t)warp * O2 + lane * 4) =
        make_float4(m0 + bv.x, m1 + bv.y, m2 + bv.z, m3 + bv.w);
}

// ---------------------------------------------------------------------------
// launch
// ---------------------------------------------------------------------------
extern "C" void kernel_launch(void* const* d_in, const int* in_sizes, int n_in,
                              void* d_out, int out_size) {
    const float* x1  = (const float*)d_in[0];
    const int*   ei1 = (const int*)  d_in[1];
    const float* ew1 = (const float*)d_in[2];
    const float* x2  = (const float*)d_in[3];
    const int*   ei2 = (const int*)  d_in[4];
    const float* ew2 = (const float*)d_in[5];
    const float* W1  = (const float*)d_in[6];
    const float* b1  = (const float*)d_in[7];
    const float* W2  = (const float*)d_in[8];
    const float* b2  = (const float*)d_in[9];
    float* out = (float*)d_out;

    const int TB = 256;
    k_init      <<<dim3((NN + TB - 1) / TB, 2), TB>>>();
    k_prep_gemm1<<<dim3(PREP_BLOCKS + G1_BLOCKS, 2), TB>>>(ei1, ew1, ei2, ew2, x1, x2, W1);
    k_scan      <<<dim3(NBLK, 2), SCAN_B>>>();
    k_fill      <<<dim3((EE + TB - 1) / TB, 2), TB>>>(ei1, ew1, ei2, ew2);

    k_aggr1<<<dim3((NN * 32 + TB - 1) / TB, 2), TB>>>(b1);
    dim3 gblk(16, 16);
    k_gemm2<<<dim3(G1_BLOCKS, 2, 2), gblk>>>(W2);
    k_aggr2<<<dim3((NN * 32 + TB - 1) / TB, 2), TB>>>(b2, out);
}